// round 1
// baseline (speedup 1.0000x reference)
#include <cuda_runtime.h>
#include <math.h>

#define IM    256
#define MTOT  184320
#define NSP   288
#define NSAM  640
#define ORTHO (1.0f/256.0f)

#define NCHUNK   96
#define M_PER_CH (MTOT/NCHUNK)   // 1920
#define MT       32              // m per adjoint stage
#define NSTAGES  (M_PER_CH/MT)   // 60

// Scratch (static device arrays: allocation-free)
__device__ float2 g_G[MTOT*IM];          // k-space rows expanded over v  (377 MB)
__device__ float2 g_Xp[NCHUNK][IM*IM];   // adjoint partials              (50 MB)

__device__ __forceinline__ float2 cmulf(float2 a, float2 b) {
    return make_float2(a.x*b.x - a.y*b.y, a.x*b.y + a.y*b.x);
}

// ---------------------------------------------------------------------------
// Forward: per block 32 m-values. Thread layout: vg = tid&31 (v lanes),
// mg = tid>>5 (8 groups x 4 m). Each thread accumulates T[m, vg+32j] for
// j=0..7 over all 256 u via phase recurrence, then reduces with Ey weights
// (warp butterfly over the 32 v-lanes), blends with measured data, and
// expands G[m, :] = k[m] * e^{+i ky v}.
// ---------------------------------------------------------------------------
__global__ __launch_bounds__(256)
void fwd_kernel(const float2* __restrict__ img,
                const float2* __restrict__ yrad,
                const float*  __restrict__ lamp,
                const float*  __restrict__ kxs,
                const float*  __restrict__ kys)
{
    __shared__ float2 img_s[16][IM];

    const int tid = threadIdx.x;
    const int vg  = tid & 31;
    const int mg  = tid >> 5;
    const int m0  = blockIdx.x * 32 + mg * 4;

    float kx[4], ky[4];
    float2 ex[4], stx[4];
#pragma unroll
    for (int i = 0; i < 4; i++) {
        kx[i] = kxs[m0 + i];
        ky[i] = kys[m0 + i];
        float s, c;
        sincosf(128.0f * kx[i], &s, &c);   // e^{-i kx * (-128)} = e^{+i 128 kx}
        ex[i]  = make_float2(c, s);
        sincosf(kx[i], &s, &c);            // step e^{-i kx}
        stx[i] = make_float2(c, -s);
    }

    float2 acc[4][8];
#pragma unroll
    for (int i = 0; i < 4; i++)
#pragma unroll
        for (int j = 0; j < 8; j++) acc[i][j] = make_float2(0.f, 0.f);

    for (int ub = 0; ub < IM; ub += 16) {
        __syncthreads();
#pragma unroll
        for (int r = 0; r < 16; r++) {
            int idx = r * 256 + tid;
            img_s[idx >> 8][idx & 255] = img[(ub + (idx >> 8)) * IM + (idx & 255)];
        }
        __syncthreads();
#pragma unroll
        for (int uu = 0; uu < 16; uu++) {
            float2 c[8];
#pragma unroll
            for (int j = 0; j < 8; j++) c[j] = img_s[uu][vg + 32 * j];
#pragma unroll
            for (int i = 0; i < 4; i++) {
                float2 e = ex[i];
#pragma unroll
                for (int j = 0; j < 8; j++) {
                    acc[i][j].x = fmaf(e.x, c[j].x, fmaf(-e.y, c[j].y, acc[i][j].x));
                    acc[i][j].y = fmaf(e.x, c[j].y, fmaf( e.y, c[j].x, acc[i][j].y));
                }
                ex[i] = cmulf(e, stx[i]);
            }
        }
    }

    const float lam  = 1.0f / (1.0f + expf(-lamp[0]));
    const float vgc  = (float)(vg - 128);

#pragma unroll
    for (int i = 0; i < 4; i++) {
        const int m = m0 + i;
        float s, c;
        sincosf(ky[i] * vgc, &s, &c);
        const float2 eyb = make_float2(c, -s);     // e^{-i ky (vg-128)}
        sincosf(ky[i] * 32.0f, &s, &c);
        const float2 eys = make_float2(c, -s);     // e^{-i 32 ky}

        float2 t = make_float2(0.f, 0.f);
        float2 e = eyb;
#pragma unroll
        for (int j = 0; j < 8; j++) {
            float2 a = acc[i][j];
            t.x = fmaf(a.x, e.x, fmaf(-a.y, e.y, t.x));
            t.y = fmaf(a.x, e.y, fmaf( a.y, e.x, t.y));
            e = cmulf(e, eys);
        }
        // reduce across all 32 v-lanes (one warp == fixed mg, vg 0..31)
#pragma unroll
        for (int o = 16; o > 0; o >>= 1) {
            t.x += __shfl_xor_sync(0xffffffffu, t.x, o);
            t.y += __shfl_xor_sync(0xffffffffu, t.y, o);
        }

        const float dcf = sqrtf(kx[i]*kx[i] + ky[i]*ky[i]);
        const int   sp  = m / NSAM;
        const int   sam = m - sp * NSAM;
        const float2 y  = yrad[sam * NSP + sp];
        const float  w  = lam * dcf * ORTHO;
        const float2 k  = make_float2(fmaf(w, t.x, (1.0f - lam) * y.x),
                                      fmaf(w, t.y, (1.0f - lam) * y.y));

        // expand G[m, v] = k * e^{+i ky (v-128)}  (conjugate recurrence)
        float2 cur = make_float2(eyb.x, -eyb.y);
        const float2 esp = make_float2(eys.x, -eys.y);
#pragma unroll
        for (int j = 0; j < 8; j++) {
            g_G[m * IM + vg + 32 * j] = cmulf(k, cur);
            cur = cmulf(cur, esp);
        }
    }
}

// ---------------------------------------------------------------------------
// Adjoint: X[u,v] = sum_m e^{+i kx_m (u-128)} * G[m,v].
// Block = (m-chunk, u-tile 64, v-tile 128). Thread: ug = tid>>4 (16 groups x
// 4 u), vg = tid&15 (16 groups x 8 v strided by 16). Phase tile staged in
// smem via per-m recurrence along u; G tile staged from global.
// Partials stored (no atomics) to g_Xp[chunk], reduced afterwards.
// ---------------------------------------------------------------------------
__global__ __launch_bounds__(256)
void adj_kernel(const float* __restrict__ kxs)
{
    __shared__ float2 Es[MT][64];
    __shared__ float2 Gs[MT][128];

    const int tid   = threadIdx.x;
    const int vg    = tid & 15;
    const int ug    = tid >> 4;
    const int chunk = blockIdx.x;
    const int u0    = blockIdx.y * 64;
    const int v0    = blockIdx.z * 128;
    const int mbase = chunk * M_PER_CH;

    float2 acc[4][8];
#pragma unroll
    for (int i = 0; i < 4; i++)
#pragma unroll
        for (int j = 0; j < 8; j++) acc[i][j] = make_float2(0.f, 0.f);

    for (int st = 0; st < NSTAGES; st++) {
        const int ms0 = mbase + st * MT;
        __syncthreads();
        // stage G tile: 32 m x 128 v
#pragma unroll
        for (int r = 0; r < 16; r++) {
            int idx = r * 256 + tid;
            int mm  = idx >> 7, vv = idx & 127;
            Gs[mm][vv] = g_G[(ms0 + mm) * IM + v0 + vv];
        }
        // stage phase tile: 32 m x 64 u via recurrence (8 u per thread)
        {
            const int mm  = tid >> 3;
            const int us0 = (tid & 7) * 8;
            const float kxv = kxs[ms0 + mm];
            float s, c;
            sincosf(kxv * (float)(u0 + us0 - 128), &s, &c);
            float2 cur = make_float2(c, s);          // e^{+i kx uc}
            sincosf(kxv, &s, &c);
            const float2 stp = make_float2(c, s);    // e^{+i kx}
#pragma unroll
            for (int q = 0; q < 8; q++) { Es[mm][us0 + q] = cur; cur = cmulf(cur, stp); }
        }
        __syncthreads();

#pragma unroll 2
        for (int mm = 0; mm < MT; mm++) {
            float2 eu[4], gv[8];
#pragma unroll
            for (int i = 0; i < 4; i++) eu[i] = Es[mm][ug * 4 + i];
#pragma unroll
            for (int j = 0; j < 8; j++) gv[j] = Gs[mm][vg + 16 * j];
#pragma unroll
            for (int i = 0; i < 4; i++)
#pragma unroll
                for (int j = 0; j < 8; j++) {
                    acc[i][j].x = fmaf(eu[i].x, gv[j].x, fmaf(-eu[i].y, gv[j].y, acc[i][j].x));
                    acc[i][j].y = fmaf(eu[i].x, gv[j].y, fmaf( eu[i].y, gv[j].x, acc[i][j].y));
                }
        }
    }

#pragma unroll
    for (int i = 0; i < 4; i++) {
        const int u = u0 + ug * 4 + i;
#pragma unroll
        for (int j = 0; j < 8; j++) {
            const int v = v0 + vg + 16 * j;
            g_Xp[chunk][u * IM + v] = acc[i][j];
        }
    }
}

// ---------------------------------------------------------------------------
// Reduce partials, scale by adjoint ORTHO, write (H,W,2) interleaved output.
// ---------------------------------------------------------------------------
__global__ __launch_bounds__(256)
void reduce_kernel(float* __restrict__ out)
{
    const int i = blockIdx.x * 256 + threadIdx.x;   // 0 .. 65535
    float sx = 0.f, sy = 0.f;
#pragma unroll 8
    for (int c = 0; c < NCHUNK; c++) {
        float2 p = g_Xp[c][i];
        sx += p.x; sy += p.y;
    }
    out[2*i + 0] = sx * ORTHO;
    out[2*i + 1] = sy * ORTHO;
}

// ---------------------------------------------------------------------------
extern "C" void kernel_launch(void* const* d_in, const int* in_sizes, int n_in,
                              void* d_out, int out_size)
{
    const float2* img  = (const float2*)d_in[0];          // (1,1,256,256,2)
    const float2* yrad = (const float2*)d_in[1];          // (640,288,2)
    const float*  lamp = (const float*)d_in[2];           // (1,)
    const float*  ktr  = (const float*)d_in[3];           // (1,2,184320)
    const float*  kxs  = ktr;
    const float*  kys  = ktr + MTOT;
    float* out = (float*)d_out;

    fwd_kernel<<<MTOT/32, 256>>>(img, yrad, lamp, kxs, kys);

    dim3 agrid(NCHUNK, IM/64, IM/128);
    adj_kernel<<<agrid, 256>>>(kxs);

    reduce_kernel<<<IM*IM/256, 256>>>(out);
}